// round 14
// baseline (speedup 1.0000x reference)
#include <cuda_runtime.h>
#include <cuda.h>
#include <cuda_bf16.h>
#include <cstdint>
#include <math.h>

#define NN 30000
#define KK 15
#define TT 400
#define NCC 5
#define GG 8                      // rows per block in main kernel
#define ROWS 16                   // self + 15 neighbors
#define ROWBYTES (TT * 2)         // 800 B per bf16 row
#define STAGEBYTES (ROWS * ROWBYTES)  // 12800 B
#define T4 (TT / 4)               // 100 chunks of 4 t-values

// ---------------- scratch (device globals: allocation-free) ----------------
__device__ __align__(32) __nv_bfloat16 g_emd[NN * TT];  // summed EMD bf16 (24 MB)
__device__ float g_tab[2 * NCC * TT];                   // sin table, cos table

// ---------------- helpers ----------------
__device__ __forceinline__ uint32_t smem_u32(const void* p) {
    uint32_t a;
    asm("{ .reg .u64 t; cvta.to.shared.u64 t, %1; cvt.u32.u64 %0, t; }"
        : "=r"(a) : "l"(p));
    return a;
}
__device__ __forceinline__ void mbar_init(uint32_t mbar, uint32_t count) {
    asm volatile("mbarrier.init.shared.b64 [%0], %1;" :: "r"(mbar), "r"(count) : "memory");
}
__device__ __forceinline__ void mbar_expect_tx(uint32_t mbar, uint32_t bytes) {
    asm volatile("mbarrier.arrive.expect_tx.shared.b64 _, [%0], %1;"
                 :: "r"(mbar), "r"(bytes) : "memory");
}
__device__ __forceinline__ void mbar_wait(uint32_t mbar, uint32_t parity) {
    asm volatile(
        "{\n\t"
        ".reg .pred P;\n\t"
        "LAB_WAIT_%=:\n\t"
        "mbarrier.try_wait.parity.acquire.cta.shared::cta.b64 P, [%0], %1, 0x989680;\n\t"
        "@P bra LAB_DONE_%=;\n\t"
        "bra LAB_WAIT_%=;\n\t"
        "LAB_DONE_%=:\n\t"
        "}"
        :: "r"(mbar), "r"(parity) : "memory");
}
__device__ __forceinline__ void bulk_g2s(uint32_t dst, const void* src,
                                         uint32_t bytes, uint32_t mbar) {
    asm volatile(
        "cp.async.bulk.shared::cluster.global.mbarrier::complete_tx::bytes "
        "[%0], [%1], %2, [%3];"
        :: "r"(dst), "l"(src), "r"(bytes), "r"(mbar) : "memory");
}
// gather4 (sm_103: destination must be .shared::cta)
__device__ __forceinline__ void g4(uint32_t dst, const CUtensorMap* tmap,
                                   int r0, int r1, int r2, int r3, uint32_t mbar) {
    asm volatile(
        "cp.async.bulk.tensor.2d.tile::gather4.shared::cta.global"
        ".mbarrier::complete_tx::bytes [%0], [%1, {%2, %3, %4, %5, %6}], [%7];"
        :: "r"(dst), "l"(tmap), "r"(0), "r"(r0), "r"(r1), "r"(r2), "r"(r3),
           "r"(mbar) : "memory");
}
// bf16 unpack: lo via shift; hi uses raw word (garbage low bits below bf16 ulp)
__device__ __forceinline__ float bf_lo(uint32_t u) { return __uint_as_float(u << 16); }
__device__ __forceinline__ float bf_hi(uint32_t u) { return __uint_as_float(u); }

// ------------- pre-pass: TAB (8 blocks) + emdsum only -----------------------
#define EMD_WORK  (NN * (TT / 8))
#define NB_EMD    ((EMD_WORK + 255) / 256)     // 5860
#define NB_TAB    ((NCC * TT + 255) / 256)     // 8
#define NB_PRE    (NB_TAB + NB_EMD)

__global__ void __launch_bounds__(256)
k_pre(const float* __restrict__ emd,
      const float* __restrict__ tv,
      const float* __restrict__ per) {
    int b = blockIdx.x;
    int tid = threadIdx.x;
    if (b < NB_TAB) {
        int i = b * 256 + tid;
        if (i < NCC * TT) {
            int c = i / TT;
            int t = i - c * TT;
            float p = fminf(fmaxf(per[c], 15.0f), 350.0f);
            float arg = 6.283185307179586f * tv[t] / p;
            float si, co;
            sincosf(arg, &si, &co);
            g_tab[i] = si;
            g_tab[NCC * TT + i] = co;
        }
        cudaTriggerProgrammaticLaunchCompletion();
        return;
    }
    b -= NB_TAB;
    {
        // ---- emdsum -> bf16 (DRAM-bound bulk) ----
        int i = b * 256 + tid;
        if (i < EMD_WORK) {
            int n = i / (TT / 8);
            int t8 = i - n * (TT / 8);
            const float4* base = reinterpret_cast<const float4*>(emd + (size_t)n * 4 * TT);
            float r[8];
#pragma unroll
            for (int e = 0; e < 8; e++) r[e] = 0.0f;
#pragma unroll
            for (int c = 0; c < 4; c++) {
                float4 a = base[c * T4 + 2 * t8];
                float4 bb = base[c * T4 + 2 * t8 + 1];
                r[0] += a.x;  r[1] += a.y;  r[2] += a.z;  r[3] += a.w;
                r[4] += bb.x; r[5] += bb.y; r[6] += bb.z; r[7] += bb.w;
            }
            __nv_bfloat162 h[4];
#pragma unroll
            for (int e = 0; e < 4; e++)
                h[e] = __floats2bfloat162_rn(r[2 * e], r[2 * e + 1]);
            reinterpret_cast<uint4*>(g_emd + (size_t)n * TT)[t8] =
                *reinterpret_cast<uint4*>(h);
        }
        cudaTriggerProgrammaticLaunchCompletion();
    }
}

// ======== shared pieces for both main kernels ================================
extern __shared__ __align__(1024) __nv_bfloat16 s_buf[];  // 2 * 12800 B

struct MainSmem {
    unsigned long long full[2];
    int   idxs[GG][ROWS];   // [0]=self, [1..15]=neighbors
    float W[GG][16];
    float UV[GG][10];
    float off[GG];
    float tr[GG];
};

// prologue A (PRE-sync): depends ONLY on harness inputs.
// Computes idx/off/tr + W + UV locally — runs in k_pre's PDL shadow.
__device__ __forceinline__ void prologue_inputs(
    MainSmem& sm, const int* __restrict__ idx,
    const float* __restrict__ coff, const float* __restrict__ ltr,
    const float* __restrict__ tv,
    const float* __restrict__ nbr_w, const float* __restrict__ loc_w,
    const float* __restrict__ esw, const float* __restrict__ lsw,
    const float* __restrict__ amp, const float* __restrict__ ph,
    int n0, int tid, float4& tv4, bool act) {
    if (tid < GG * KK) sm.idxs[tid / KK][tid % KK + 1] = idx[n0 * KK + tid];
    if (tid < GG) {
        sm.off[tid] = coff[n0 + tid];
        sm.tr[tid] = ltr[n0 + tid];
        sm.idxs[tid][0] = n0 + tid;
    }
    if (tid == 0) {
        uint32_t f0 = smem_u32(&sm.full[0]);
        mbar_init(f0, 1);
        mbar_init(f0 + 8, 1);
        asm volatile("fence.proxy.async.shared::cta;" ::: "memory");
    }
    if (act) tv4 = reinterpret_cast<const float4*>(tv)[tid];

    // ---- W: 128 entries, one per thread ----
    {
        int g = tid >> 4, j = tid & 15;
        int n = n0 + g;
        float ew = 1.0f / (1.0f + __expf(-esw[n]));
        float wv;
        if (j == 0) {
            wv = 1.0f - ew;
        } else {
            float lw = 1.0f / (1.0f + __expf(-lsw[n]));
            int k = j - 1;
            wv = ew * lw * loc_w[n * KK + k] + ew * (1.0f - lw) * nbr_w[n * KK + k];
        }
        sm.W[g][j] = wv;
    }
    // ---- UV: GG*NCC = 40 channels on threads 0..39 ----
    if (tid < GG * NCC) {
        int g = tid / NCC, c = tid - (tid / NCC) * NCC;
        int n = n0 + g;
        float sa = 0.0f, ss = 0.0f, sc = 0.0f;
#pragma unroll
        for (int k = 0; k < KK; k++) {
            int m = idx[n * KK + k];
            float w = nbr_w[n * KK + k];
            sa += w * amp[m * NCC + c];
            float si, co;
            __sincosf(ph[m * NCC + c], &si, &co);
            ss += w * si;
            sc += w * co;
        }
        float A = 0.8f * amp[n * NCC + c] + 0.2f * sa;
        float P = 0.8f * ph[n * NCC + c] + 0.2f * atan2f(ss, sc);
        float sp, cp;
        __sincosf(P, &sp, &cp);
        sm.UV[g][c] = A * cp;
        sm.UV[g][5 + c] = A * sp;
    }
}

// prologue B (POST-sync): register sin/cos table from g_tab (k_pre output)
__device__ __forceinline__ void prologue_tables(
    int tid, float4* st, float4* ct, bool act) {
    if (act) {
#pragma unroll
        for (int c = 0; c < NCC; c++) {
            st[c] = reinterpret_cast<const float4*>(g_tab + c * TT)[tid];
            ct[c] = reinterpret_cast<const float4*>(g_tab + NCC * TT + c * TT)[tid];
        }
    }
}

__device__ __forceinline__ void stage_compute(
    MainSmem& sm, int i, int n, int tid, bool act,
    const float4* st, const float4* ct, float4 tv4, float* __restrict__ out) {
    if (!act) return;
    const uint32_t* rows = reinterpret_cast<const uint32_t*>(
        s_buf + (size_t)(i & 1) * (ROWS * TT));
    float off = sm.off[i], tr = sm.tr[i];
    float4 acc;
    acc.x = fmaf(tr, tv4.x, off);
    acc.y = fmaf(tr, tv4.y, off);
    acc.z = fmaf(tr, tv4.z, off);
    acc.w = fmaf(tr, tv4.w, off);
#pragma unroll
    for (int c = 0; c < NCC; c++) {
        float u = sm.UV[i][c], v = sm.UV[i][5 + c];
        acc.x = fmaf(u, st[c].x, fmaf(v, ct[c].x, acc.x));
        acc.y = fmaf(u, st[c].y, fmaf(v, ct[c].y, acc.y));
        acc.z = fmaf(u, st[c].z, fmaf(v, ct[c].z, acc.z));
        acc.w = fmaf(u, st[c].w, fmaf(v, ct[c].w, acc.w));
    }
#pragma unroll
    for (int j = 0; j < ROWS; j++) {
        uint2 raw = *reinterpret_cast<const uint2*>(rows + j * 200 + 2 * tid);
        float w = sm.W[i][j];
        acc.x = fmaf(w, bf_lo(raw.x), acc.x);
        acc.y = fmaf(w, bf_hi(raw.x), acc.y);
        acc.z = fmaf(w, bf_lo(raw.y), acc.z);
        acc.w = fmaf(w, bf_hi(raw.y), acc.w);
    }
    reinterpret_cast<float4*>(out + (size_t)n * TT)[tid] = acc;
}

// ---------------- k_main_g4: gather4 path (4 TMA requests per stage) --------
__global__ void __launch_bounds__(128, 8)
k_main_g4(const __grid_constant__ CUtensorMap tmap,
          const int* __restrict__ idx,
          const float* __restrict__ coff,
          const float* __restrict__ ltr,
          const float* __restrict__ tv,
          const float* __restrict__ nbr_w,
          const float* __restrict__ loc_w,
          const float* __restrict__ esw,
          const float* __restrict__ lsw,
          const float* __restrict__ amp,
          const float* __restrict__ ph,
          float* __restrict__ out) {
    __shared__ MainSmem sm;
    int tid = threadIdx.x;
    int n0 = blockIdx.x * GG;
    bool act = (tid < T4);
    float4 st[NCC], ct[NCC], tv4;
    prologue_inputs(sm, idx, coff, ltr, tv, nbr_w, loc_w, esw, lsw, amp, ph,
                    n0, tid, tv4, act);

    cudaGridDependencySynchronize();   // PDL: g_emd/g_tab visible after this

    prologue_tables(tid, st, ct, act);
    __syncthreads();

    uint32_t full0 = smem_u32(&sm.full[0]);
    uint32_t bufb  = smem_u32(s_buf);

    auto issue = [&](int s) {
        uint32_t dst = bufb + (uint32_t)(s & 1) * STAGEBYTES;
        uint32_t mb  = full0 + (uint32_t)(s & 1) * 8;
        mbar_expect_tx(mb, STAGEBYTES);
        const int* r = sm.idxs[s];
#pragma unroll
        for (int q = 0; q < 4; q++) {
            g4(dst + (uint32_t)q * (4 * ROWBYTES), &tmap,
               r[4 * q], r[4 * q + 1], r[4 * q + 2], r[4 * q + 3], mb);
        }
    };

    if (tid == 0) issue(0);
    for (int i = 0; i < GG; i++) {
        if (tid == 0 && i + 1 < GG) issue(i + 1);
        mbar_wait(full0 + (uint32_t)(i & 1) * 8, (uint32_t)((i >> 1) & 1));
        stage_compute(sm, i, n0 + i, tid, act, st, ct, tv4, out);
        __syncthreads();
    }
}

// ---------------- k_main_fb: bulk-copy fallback ------------------------------
__global__ void __launch_bounds__(128, 8)
k_main_fb(const int* __restrict__ idx,
          const float* __restrict__ coff,
          const float* __restrict__ ltr,
          const float* __restrict__ tv,
          const float* __restrict__ nbr_w,
          const float* __restrict__ loc_w,
          const float* __restrict__ esw,
          const float* __restrict__ lsw,
          const float* __restrict__ amp,
          const float* __restrict__ ph,
          float* __restrict__ out) {
    __shared__ MainSmem sm;
    int tid = threadIdx.x;
    int n0 = blockIdx.x * GG;
    bool act = (tid < T4);
    float4 st[NCC], ct[NCC], tv4;
    prologue_inputs(sm, idx, coff, ltr, tv, nbr_w, loc_w, esw, lsw, amp, ph,
                    n0, tid, tv4, act);

    cudaGridDependencySynchronize();

    prologue_tables(tid, st, ct, act);
    __syncthreads();

    uint32_t full0 = smem_u32(&sm.full[0]);
    uint32_t bufb  = smem_u32(s_buf);

    auto issue = [&](int s) {
        uint32_t dst = bufb + (uint32_t)(s & 1) * STAGEBYTES;
        uint32_t mb  = full0 + (uint32_t)(s & 1) * 8;
        mbar_expect_tx(mb, STAGEBYTES);
#pragma unroll
        for (int k = 0; k < ROWS; k++) {
            bulk_g2s(dst + (uint32_t)k * ROWBYTES,
                     g_emd + (size_t)sm.idxs[s][k] * TT, ROWBYTES, mb);
        }
    };

    if (tid == 0) issue(0);
    for (int i = 0; i < GG; i++) {
        if (tid == 0 && i + 1 < GG) issue(i + 1);
        mbar_wait(full0 + (uint32_t)(i & 1) * 8, (uint32_t)((i >> 1) & 1));
        stage_compute(sm, i, n0 + i, tid, act, st, ct, tv4, out);
        __syncthreads();
    }
}

// ---------------- launch ----------------
typedef CUresult (*EncodeFn)(CUtensorMap*, CUtensorMapDataType, cuuint32_t,
                             void*, const cuuint64_t*, const cuuint64_t*,
                             const cuuint32_t*, const cuuint32_t*,
                             CUtensorMapInterleave, CUtensorMapSwizzle,
                             CUtensorMapL2promotion, CUtensorMapFloatOOBfill);

extern "C" void kernel_launch(void* const* d_in, const int* in_sizes, int n_in,
                              void* d_out, int out_size) {
    const float* tv   = (const float*)d_in[0];
    const float* coff = (const float*)d_in[1];
    const float* ltr  = (const float*)d_in[2];
    const float* emd  = (const float*)d_in[3];
    const int*   idx  = (const int*)  d_in[4];
    const float* nw   = (const float*)d_in[5];
    const float* lwv  = (const float*)d_in[6];
    const float* amp  = (const float*)d_in[7];
    const float* ph   = (const float*)d_in[8];
    const float* per  = (const float*)d_in[9];
    const float* esw  = (const float*)d_in[10];
    const float* lsw  = (const float*)d_in[11];
    float* out = (float*)d_out;

    k_pre<<<NB_PRE, 256>>>(emd, tv, per);

    // Build gather4 tensormap: view g_emd as u32 tensor [NN rows x 200 cols]
    bool g4ok = false;
    CUtensorMap tmap;
    {
        void* fn = nullptr;
        cudaDriverEntryPointQueryResult qres;
        if (cudaGetDriverEntryPoint("cuTensorMapEncodeTiled", &fn,
                                    cudaEnableDefault, &qres) == cudaSuccess &&
            fn != nullptr) {
            void* gaddr = nullptr;
            if (cudaGetSymbolAddress(&gaddr, g_emd) == cudaSuccess) {
                cuuint64_t dims[2]    = {200, NN};
                cuuint64_t strides[1] = {ROWBYTES};   // 800 B between rows
                cuuint32_t box[2]     = {200, 1};
                cuuint32_t estr[2]    = {1, 1};
                CUresult r = ((EncodeFn)fn)(
                    &tmap, CU_TENSOR_MAP_DATA_TYPE_UINT32, 2, gaddr,
                    dims, strides, box, estr,
                    CU_TENSOR_MAP_INTERLEAVE_NONE, CU_TENSOR_MAP_SWIZZLE_NONE,
                    CU_TENSOR_MAP_L2_PROMOTION_L2_128B,
                    CU_TENSOR_MAP_FLOAT_OOB_FILL_NONE);
                g4ok = (r == CUDA_SUCCESS);
            }
        }
    }

    cudaFuncSetAttribute(k_main_g4, cudaFuncAttributeMaxDynamicSharedMemorySize,
                         2 * STAGEBYTES);
    cudaFuncSetAttribute(k_main_fb, cudaFuncAttributeMaxDynamicSharedMemorySize,
                         2 * STAGEBYTES);

    // PDL launch: k_main's prologue (incl. W/UV compute) overlaps k_pre
    cudaLaunchConfig_t cfg = {};
    cfg.gridDim = dim3(NN / GG, 1, 1);
    cfg.blockDim = dim3(128, 1, 1);
    cfg.dynamicSmemBytes = 2 * STAGEBYTES;
    cudaLaunchAttribute attrs[1];
    attrs[0].id = cudaLaunchAttributeProgrammaticStreamSerialization;
    attrs[0].val.programmaticStreamSerializationAllowed = 1;
    cfg.attrs = attrs;
    cfg.numAttrs = 1;

    if (g4ok) {
        cudaError_t e = cudaLaunchKernelEx(&cfg, k_main_g4, tmap, idx, coff, ltr,
                                           tv, nw, lwv, esw, lsw, amp, ph, out);
        if (e != cudaSuccess)
            k_main_g4<<<NN / GG, 128, 2 * STAGEBYTES>>>(
                tmap, idx, coff, ltr, tv, nw, lwv, esw, lsw, amp, ph, out);
    } else {
        cudaError_t e = cudaLaunchKernelEx(&cfg, k_main_fb, idx, coff, ltr,
                                           tv, nw, lwv, esw, lsw, amp, ph, out);
        if (e != cudaSuccess)
            k_main_fb<<<NN / GG, 128, 2 * STAGEBYTES>>>(
                idx, coff, ltr, tv, nw, lwv, esw, lsw, amp, ph, out);
    }
}

// round 15
// speedup vs baseline: 1.0258x; 1.0258x over previous
#include <cuda_runtime.h>
#include <cuda.h>
#include <cuda_bf16.h>
#include <cstdint>
#include <math.h>

#define NN 30000
#define KK 15
#define TT 400
#define NCC 5
#define GG 16                     // rows per block in main kernel
#define ROWS 16                   // self + 15 neighbors
#define ROWBYTES (TT * 2)         // 800 B per bf16 row
#define STAGEBYTES (ROWS * ROWBYTES)  // 12800 B
#define T4 (TT / 4)               // 100 chunks of 4 t-values

// ---------------- scratch (device globals: allocation-free) ----------------
__device__ __align__(32) __nv_bfloat16 g_emd[NN * TT];  // summed EMD bf16 (24 MB)
__device__ float g_W[NN * 16];
__device__ float g_UV[NN * 10];
__device__ float g_tab[2 * NCC * TT];

// ---------------- helpers ----------------
__device__ __forceinline__ uint32_t smem_u32(const void* p) {
    uint32_t a;
    asm("{ .reg .u64 t; cvta.to.shared.u64 t, %1; cvt.u32.u64 %0, t; }"
        : "=r"(a) : "l"(p));
    return a;
}
__device__ __forceinline__ void mbar_init(uint32_t mbar, uint32_t count) {
    asm volatile("mbarrier.init.shared.b64 [%0], %1;" :: "r"(mbar), "r"(count) : "memory");
}
__device__ __forceinline__ void mbar_expect_tx(uint32_t mbar, uint32_t bytes) {
    asm volatile("mbarrier.arrive.expect_tx.shared.b64 _, [%0], %1;"
                 :: "r"(mbar), "r"(bytes) : "memory");
}
__device__ __forceinline__ void mbar_wait(uint32_t mbar, uint32_t parity) {
    asm volatile(
        "{\n\t"
        ".reg .pred P;\n\t"
        "LAB_WAIT_%=:\n\t"
        "mbarrier.try_wait.parity.acquire.cta.shared::cta.b64 P, [%0], %1, 0x989680;\n\t"
        "@P bra LAB_DONE_%=;\n\t"
        "bra LAB_WAIT_%=;\n\t"
        "LAB_DONE_%=:\n\t"
        "}"
        :: "r"(mbar), "r"(parity) : "memory");
}
__device__ __forceinline__ void bulk_g2s(uint32_t dst, const void* src,
                                         uint32_t bytes, uint32_t mbar) {
    asm volatile(
        "cp.async.bulk.shared::cluster.global.mbarrier::complete_tx::bytes "
        "[%0], [%1], %2, [%3];"
        :: "r"(dst), "l"(src), "r"(bytes), "r"(mbar) : "memory");
}
// gather4 (sm_103: destination must be .shared::cta)
__device__ __forceinline__ void g4(uint32_t dst, const CUtensorMap* tmap,
                                   int r0, int r1, int r2, int r3, uint32_t mbar) {
    asm volatile(
        "cp.async.bulk.tensor.2d.tile::gather4.shared::cta.global"
        ".mbarrier::complete_tx::bytes [%0], [%1, {%2, %3, %4, %5, %6}], [%7];"
        :: "r"(dst), "l"(tmap), "r"(0), "r"(r0), "r"(r1), "r"(r2), "r"(r3),
           "r"(mbar) : "memory");
}
// bf16 unpack: lo via shift; hi uses raw word (garbage low bits below bf16 ulp)
__device__ __forceinline__ float bf_lo(uint32_t u) { return __uint_as_float(u << 16); }
__device__ __forceinline__ float bf_hi(uint32_t u) { return __uint_as_float(u); }

// fast atan2: minimax atan on [0,1] + quadrant fixup; |err| ~1e-4 rad.
// Phase enters with weight 0.2 -> output impact ~1e-5 (negligible vs 2.2e-4).
__device__ __forceinline__ float fast_atan2(float y, float x) {
    float ax = fabsf(x), ay = fabsf(y);
    float mx = fmaxf(ax, ay) + 1e-30f;
    float mn = fminf(ax, ay);
    float t = __fdividef(mn, mx);
    float s = t * t;
    float r = fmaf(fmaf(fmaf(-0.0464964749f, s, 0.15931422f), s, -0.327622764f),
                   s * t, t);
    if (ay > ax) r = 1.57079632679f - r;
    if (x < 0.0f) r = 3.14159265359f - r;
    return (y < 0.0f) ? -r : r;
}

// ------------- fused pre-pass: emdsum interleaved 2:1 with small work -------
#define EMD_WORK  (NN * (TT / 8))
#define NB_EMD    ((EMD_WORK + 255) / 256)     // 5860
#define NB_W      ((NN * 16 + 255) / 256)      // 1875
#define NB_UV     ((NN * NCC + 255) / 256)     // 586
#define NB_TAB    ((NCC * TT + 255) / 256)     // 8
#define NB_SMALL  (NB_UV + NB_W + NB_TAB)      // 2469
#define NB_PRE    (NB_EMD + NB_SMALL)          // 8329

__global__ void __launch_bounds__(256)
k_pre(const float* __restrict__ emd,
      const float* __restrict__ nbr_w,
      const float* __restrict__ loc_w,
      const float* __restrict__ esw,
      const float* __restrict__ lsw,
      const float* __restrict__ amp,
      const float* __restrict__ ph,
      const int*   __restrict__ idx,
      const float* __restrict__ tv,
      const float* __restrict__ per) {
    int b = blockIdx.x;
    int tid = threadIdx.x;
    bool is_small = ((b % 3) == 2) && (b / 3 < NB_SMALL);

    if (!is_small) {
        // ---- emdsum -> bf16 (DRAM-bound bulk) ----
        int nsmall_before = min((b + 1) / 3, NB_SMALL);
        int eb = b - nsmall_before;
        int i = eb * 256 + tid;
        if (i < EMD_WORK) {
            int n = i / (TT / 8);
            int t8 = i - n * (TT / 8);
            const float4* base = reinterpret_cast<const float4*>(emd + (size_t)n * 4 * TT);
            float r[8];
#pragma unroll
            for (int e = 0; e < 8; e++) r[e] = 0.0f;
#pragma unroll
            for (int c = 0; c < 4; c++) {
                float4 a = base[c * T4 + 2 * t8];
                float4 bb = base[c * T4 + 2 * t8 + 1];
                r[0] += a.x;  r[1] += a.y;  r[2] += a.z;  r[3] += a.w;
                r[4] += bb.x; r[5] += bb.y; r[6] += bb.z; r[7] += bb.w;
            }
            __nv_bfloat162 h[4];
#pragma unroll
            for (int e = 0; e < 4; e++)
                h[e] = __floats2bfloat162_rn(r[2 * e], r[2 * e + 1]);
            reinterpret_cast<uint4*>(g_emd + (size_t)n * TT)[t8] =
                *reinterpret_cast<uint4*>(h);
        }
        cudaTriggerProgrammaticLaunchCompletion();
        return;
    }

    int s = b / 3;   // small-work id, UV first (longest latency chains)
    if (s < NB_UV) {
        int i = s * 256 + tid;
        if (i < NN * NCC) {
            int n = i / NCC;
            int c = i - n * NCC;
            float sa = 0.0f, ss = 0.0f, sc = 0.0f;
#pragma unroll
            for (int k = 0; k < KK; k++) {
                int m = idx[n * KK + k];
                float w = nbr_w[n * KK + k];
                sa += w * amp[m * NCC + c];
                float p = ph[m * NCC + c];
                float si, co;
                __sincosf(p, &si, &co);
                ss += w * si;
                sc += w * co;
            }
            float A = 0.8f * amp[i] + 0.2f * sa;
            float P = 0.8f * ph[i] + 0.2f * fast_atan2(ss, sc);
            float sp, cp;
            __sincosf(P, &sp, &cp);
            g_UV[n * 10 + c] = A * cp;
            g_UV[n * 10 + 5 + c] = A * sp;
        }
        cudaTriggerProgrammaticLaunchCompletion();
        return;
    }
    s -= NB_UV;
    if (s < NB_W) {
        int i = s * 256 + tid;
        if (i < NN * 16) {
            int n = i >> 4;
            int j = i & 15;
            float ew = 1.0f / (1.0f + __expf(-esw[n]));
            if (j == 0) {
                g_W[i] = 1.0f - ew;
            } else {
                float lw = 1.0f / (1.0f + __expf(-lsw[n]));
                int k = j - 1;
                g_W[i] = ew * lw * loc_w[n * KK + k]
                       + ew * (1.0f - lw) * nbr_w[n * KK + k];
            }
        }
        cudaTriggerProgrammaticLaunchCompletion();
        return;
    }
    s -= NB_W;
    {
        int i = s * 256 + tid;
        if (i < NCC * TT) {
            int c = i / TT;
            int t = i - c * TT;
            float p = fminf(fmaxf(per[c], 15.0f), 350.0f);
            float arg = 6.283185307179586f * tv[t] / p;
            float si, co;
            sincosf(arg, &si, &co);
            g_tab[i] = si;
            g_tab[NCC * TT + i] = co;
        }
        cudaTriggerProgrammaticLaunchCompletion();
    }
}

// ======== shared compute body for both main kernels =========================
extern __shared__ __align__(1024) __nv_bfloat16 s_buf[];  // 2 * 12800 B

struct MainSmem {
    unsigned long long full[2];
    int   idxs[GG][ROWS];   // [0]=self, [1..15]=neighbors
    float W[GG][16];
    float UV[GG][10];
    float off[GG];
    float tr[GG];
};

// prologue A: depends ONLY on harness inputs — safe before griddep sync
__device__ __forceinline__ void prologue_inputs(
    MainSmem& sm, const int* __restrict__ idx,
    const float* __restrict__ coff, const float* __restrict__ ltr,
    const float* __restrict__ tv, int n0, int tid, float4& tv4, bool act) {
    for (int j = tid; j < GG * KK; j += 128)
        sm.idxs[j / KK][j % KK + 1] = idx[n0 * KK + j];
    if (tid < GG) {
        sm.off[tid] = coff[n0 + tid];
        sm.tr[tid] = ltr[n0 + tid];
        sm.idxs[tid][0] = n0 + tid;
    }
    if (tid == 0) {
        uint32_t f0 = smem_u32(&sm.full[0]);
        mbar_init(f0, 1);
        mbar_init(f0 + 8, 1);
        asm volatile("fence.proxy.async.shared::cta;" ::: "memory");
    }
    if (act) tv4 = reinterpret_cast<const float4*>(tv)[tid];
}

// prologue B: reads pre-pass outputs — AFTER griddep sync.
// Register-resident sin/cos table (proven — do NOT evict).
__device__ __forceinline__ void prologue_tables(
    MainSmem& sm, int n0, int tid, float4* st, float4* ct, bool act) {
    for (int j = tid; j < GG * 16; j += 128)
        sm.W[j >> 4][j & 15] = g_W[n0 * 16 + j];
    for (int j = tid; j < GG * 10; j += 128)
        sm.UV[j / 10][j % 10] = g_UV[n0 * 10 + j];
    if (act) {
#pragma unroll
        for (int c = 0; c < NCC; c++) {
            st[c] = reinterpret_cast<const float4*>(g_tab + c * TT)[tid];
            ct[c] = reinterpret_cast<const float4*>(g_tab + NCC * TT + c * TT)[tid];
        }
    }
}

__device__ __forceinline__ void stage_compute(
    MainSmem& sm, int i, int n, int tid, bool act,
    const float4* st, const float4* ct, float4 tv4, float* __restrict__ out) {
    if (!act) return;
    const uint32_t* rows = reinterpret_cast<const uint32_t*>(
        s_buf + (size_t)(i & 1) * (ROWS * TT));
    float off = sm.off[i], tr = sm.tr[i];
    float4 acc;
    acc.x = fmaf(tr, tv4.x, off);
    acc.y = fmaf(tr, tv4.y, off);
    acc.z = fmaf(tr, tv4.z, off);
    acc.w = fmaf(tr, tv4.w, off);
#pragma unroll
    for (int c = 0; c < NCC; c++) {
        float u = sm.UV[i][c], v = sm.UV[i][5 + c];
        acc.x = fmaf(u, st[c].x, fmaf(v, ct[c].x, acc.x));
        acc.y = fmaf(u, st[c].y, fmaf(v, ct[c].y, acc.y));
        acc.z = fmaf(u, st[c].z, fmaf(v, ct[c].z, acc.z));
        acc.w = fmaf(u, st[c].w, fmaf(v, ct[c].w, acc.w));
    }
#pragma unroll
    for (int j = 0; j < ROWS; j++) {
        uint2 raw = *reinterpret_cast<const uint2*>(rows + j * 200 + 2 * tid);
        float w = sm.W[i][j];
        acc.x = fmaf(w, bf_lo(raw.x), acc.x);
        acc.y = fmaf(w, bf_hi(raw.x), acc.y);
        acc.z = fmaf(w, bf_lo(raw.y), acc.z);
        acc.w = fmaf(w, bf_hi(raw.y), acc.w);
    }
    reinterpret_cast<float4*>(out + (size_t)n * TT)[tid] = acc;
}

// ---------------- k_main_g4: gather4 path (4 TMA requests per stage) --------
__global__ void __launch_bounds__(128, 8)
k_main_g4(const __grid_constant__ CUtensorMap tmap,
          const int* __restrict__ idx,
          const float* __restrict__ coff,
          const float* __restrict__ ltr,
          const float* __restrict__ tv,
          float* __restrict__ out) {
    __shared__ MainSmem sm;
    int tid = threadIdx.x;
    int n0 = blockIdx.x * GG;
    bool act = (tid < T4);
    float4 st[NCC], ct[NCC], tv4;
    prologue_inputs(sm, idx, coff, ltr, tv, n0, tid, tv4, act);

    cudaGridDependencySynchronize();   // PDL: g_* visible after this

    prologue_tables(sm, n0, tid, st, ct, act);
    __syncthreads();

    uint32_t full0 = smem_u32(&sm.full[0]);
    uint32_t bufb  = smem_u32(s_buf);

    auto issue = [&](int s) {
        uint32_t dst = bufb + (uint32_t)(s & 1) * STAGEBYTES;
        uint32_t mb  = full0 + (uint32_t)(s & 1) * 8;
        mbar_expect_tx(mb, STAGEBYTES);
        const int* r = sm.idxs[s];
#pragma unroll
        for (int q = 0; q < 4; q++) {
            g4(dst + (uint32_t)q * (4 * ROWBYTES), &tmap,
               r[4 * q], r[4 * q + 1], r[4 * q + 2], r[4 * q + 3], mb);
        }
    };

    if (tid == 0) issue(0);
    for (int i = 0; i < GG; i++) {
        if (tid == 0 && i + 1 < GG) issue(i + 1);
        mbar_wait(full0 + (uint32_t)(i & 1) * 8, (uint32_t)((i >> 1) & 1));
        stage_compute(sm, i, n0 + i, tid, act, st, ct, tv4, out);
        __syncthreads();
    }
}

// ---------------- k_main_fb: bulk-copy fallback ------------------------------
__global__ void __launch_bounds__(128, 8)
k_main_fb(const int* __restrict__ idx,
          const float* __restrict__ coff,
          const float* __restrict__ ltr,
          const float* __restrict__ tv,
          float* __restrict__ out) {
    __shared__ MainSmem sm;
    int tid = threadIdx.x;
    int n0 = blockIdx.x * GG;
    bool act = (tid < T4);
    float4 st[NCC], ct[NCC], tv4;
    prologue_inputs(sm, idx, coff, ltr, tv, n0, tid, tv4, act);

    cudaGridDependencySynchronize();

    prologue_tables(sm, n0, tid, st, ct, act);
    __syncthreads();

    uint32_t full0 = smem_u32(&sm.full[0]);
    uint32_t bufb  = smem_u32(s_buf);

    auto issue = [&](int s) {
        uint32_t dst = bufb + (uint32_t)(s & 1) * STAGEBYTES;
        uint32_t mb  = full0 + (uint32_t)(s & 1) * 8;
        mbar_expect_tx(mb, STAGEBYTES);
#pragma unroll
        for (int k = 0; k < ROWS; k++) {
            bulk_g2s(dst + (uint32_t)k * ROWBYTES,
                     g_emd + (size_t)sm.idxs[s][k] * TT, ROWBYTES, mb);
        }
    };

    if (tid == 0) issue(0);
    for (int i = 0; i < GG; i++) {
        if (tid == 0 && i + 1 < GG) issue(i + 1);
        mbar_wait(full0 + (uint32_t)(i & 1) * 8, (uint32_t)((i >> 1) & 1));
        stage_compute(sm, i, n0 + i, tid, act, st, ct, tv4, out);
        __syncthreads();
    }
}

// ---------------- launch ----------------
typedef CUresult (*EncodeFn)(CUtensorMap*, CUtensorMapDataType, cuuint32_t,
                             void*, const cuuint64_t*, const cuuint64_t*,
                             const cuuint32_t*, const cuuint32_t*,
                             CUtensorMapInterleave, CUtensorMapSwizzle,
                             CUtensorMapL2promotion, CUtensorMapFloatOOBfill);

extern "C" void kernel_launch(void* const* d_in, const int* in_sizes, int n_in,
                              void* d_out, int out_size) {
    const float* tv   = (const float*)d_in[0];
    const float* coff = (const float*)d_in[1];
    const float* ltr  = (const float*)d_in[2];
    const float* emd  = (const float*)d_in[3];
    const int*   idx  = (const int*)  d_in[4];
    const float* nw   = (const float*)d_in[5];
    const float* lwv  = (const float*)d_in[6];
    const float* amp  = (const float*)d_in[7];
    const float* ph   = (const float*)d_in[8];
    const float* per  = (const float*)d_in[9];
    const float* esw  = (const float*)d_in[10];
    const float* lsw  = (const float*)d_in[11];
    float* out = (float*)d_out;

    k_pre<<<NB_PRE, 256>>>(emd, nw, lwv, esw, lsw, amp, ph, idx, tv, per);

    // Build gather4 tensormap: view g_emd as u32 tensor [NN rows x 200 cols]
    bool g4ok = false;
    CUtensorMap tmap;
    {
        void* fn = nullptr;
        cudaDriverEntryPointQueryResult qres;
        if (cudaGetDriverEntryPoint("cuTensorMapEncodeTiled", &fn,
                                    cudaEnableDefault, &qres) == cudaSuccess &&
            fn != nullptr) {
            void* gaddr = nullptr;
            if (cudaGetSymbolAddress(&gaddr, g_emd) == cudaSuccess) {
                cuuint64_t dims[2]    = {200, NN};
                cuuint64_t strides[1] = {ROWBYTES};   // 800 B between rows
                cuuint32_t box[2]     = {200, 1};
                cuuint32_t estr[2]    = {1, 1};
                CUresult r = ((EncodeFn)fn)(
                    &tmap, CU_TENSOR_MAP_DATA_TYPE_UINT32, 2, gaddr,
                    dims, strides, box, estr,
                    CU_TENSOR_MAP_INTERLEAVE_NONE, CU_TENSOR_MAP_SWIZZLE_NONE,
                    CU_TENSOR_MAP_L2_PROMOTION_L2_128B,
                    CU_TENSOR_MAP_FLOAT_OOB_FILL_NONE);
                g4ok = (r == CUDA_SUCCESS);
            }
        }
    }

    cudaFuncSetAttribute(k_main_g4, cudaFuncAttributeMaxDynamicSharedMemorySize,
                         2 * STAGEBYTES);
    cudaFuncSetAttribute(k_main_fb, cudaFuncAttributeMaxDynamicSharedMemorySize,
                         2 * STAGEBYTES);

    // PDL launch: k_main's launch + input-only prologue overlap k_pre's tail
    cudaLaunchConfig_t cfg = {};
    cfg.gridDim = dim3(NN / GG, 1, 1);
    cfg.blockDim = dim3(128, 1, 1);
    cfg.dynamicSmemBytes = 2 * STAGEBYTES;
    cudaLaunchAttribute attrs[1];
    attrs[0].id = cudaLaunchAttributeProgrammaticStreamSerialization;
    attrs[0].val.programmaticStreamSerializationAllowed = 1;
    cfg.attrs = attrs;
    cfg.numAttrs = 1;

    if (g4ok) {
        cudaError_t e = cudaLaunchKernelEx(&cfg, k_main_g4,
                                           tmap, idx, coff, ltr, tv, out);
        if (e != cudaSuccess)
            k_main_g4<<<NN / GG, 128, 2 * STAGEBYTES>>>(tmap, idx, coff, ltr, tv, out);
    } else {
        cudaError_t e = cudaLaunchKernelEx(&cfg, k_main_fb,
                                           idx, coff, ltr, tv, out);
        if (e != cudaSuccess)
            k_main_fb<<<NN / GG, 128, 2 * STAGEBYTES>>>(idx, coff, ltr, tv, out);
    }
}

// round 16
// speedup vs baseline: 1.0772x; 1.0501x over previous
#include <cuda_runtime.h>
#include <cuda.h>
#include <cuda_bf16.h>
#include <cstdint>
#include <math.h>

#define NN 30000
#define KK 15
#define TT 400
#define NCC 5
#define GG 8                      // rows per block in main kernel
#define ROWS 16                   // self + 15 neighbors
#define ROWBYTES (TT * 2)         // 800 B per bf16 row
#define STAGEBYTES (ROWS * ROWBYTES)  // 12800 B
#define T4 (TT / 4)               // 100 chunks of 4 t-values

// ---------------- scratch (device globals: allocation-free) ----------------
__device__ __align__(32) __nv_bfloat16 g_emd[NN * TT];  // summed EMD bf16 (24 MB)
__device__ float g_W[NN * 16];
__device__ float g_UV[NN * 10];
__device__ float g_tab[2 * NCC * TT];

// ---------------- helpers ----------------
__device__ __forceinline__ uint32_t smem_u32(const void* p) {
    uint32_t a;
    asm("{ .reg .u64 t; cvta.to.shared.u64 t, %1; cvt.u32.u64 %0, t; }"
        : "=r"(a) : "l"(p));
    return a;
}
__device__ __forceinline__ void mbar_init(uint32_t mbar, uint32_t count) {
    asm volatile("mbarrier.init.shared.b64 [%0], %1;" :: "r"(mbar), "r"(count) : "memory");
}
__device__ __forceinline__ void mbar_expect_tx(uint32_t mbar, uint32_t bytes) {
    asm volatile("mbarrier.arrive.expect_tx.shared.b64 _, [%0], %1;"
                 :: "r"(mbar), "r"(bytes) : "memory");
}
__device__ __forceinline__ void mbar_wait(uint32_t mbar, uint32_t parity) {
    asm volatile(
        "{\n\t"
        ".reg .pred P;\n\t"
        "LAB_WAIT_%=:\n\t"
        "mbarrier.try_wait.parity.acquire.cta.shared::cta.b64 P, [%0], %1, 0x989680;\n\t"
        "@P bra LAB_DONE_%=;\n\t"
        "bra LAB_WAIT_%=;\n\t"
        "LAB_DONE_%=:\n\t"
        "}"
        :: "r"(mbar), "r"(parity) : "memory");
}
__device__ __forceinline__ void bulk_g2s(uint32_t dst, const void* src,
                                         uint32_t bytes, uint32_t mbar) {
    asm volatile(
        "cp.async.bulk.shared::cluster.global.mbarrier::complete_tx::bytes "
        "[%0], [%1], %2, [%3];"
        :: "r"(dst), "l"(src), "r"(bytes), "r"(mbar) : "memory");
}
// gather4 (sm_103: destination must be .shared::cta)
__device__ __forceinline__ void g4(uint32_t dst, const CUtensorMap* tmap,
                                   int r0, int r1, int r2, int r3, uint32_t mbar) {
    asm volatile(
        "cp.async.bulk.tensor.2d.tile::gather4.shared::cta.global"
        ".mbarrier::complete_tx::bytes [%0], [%1, {%2, %3, %4, %5, %6}], [%7];"
        :: "r"(dst), "l"(tmap), "r"(0), "r"(r0), "r"(r1), "r"(r2), "r"(r3),
           "r"(mbar) : "memory");
}
// bf16 unpack: lo via shift; hi uses raw word (garbage low bits below bf16 ulp)
__device__ __forceinline__ float bf_lo(uint32_t u) { return __uint_as_float(u << 16); }
__device__ __forceinline__ float bf_hi(uint32_t u) { return __uint_as_float(u); }

// fast atan2: minimax atan on [0,1] + quadrant fixup; |err| ~1e-4 rad.
// Phase enters with weight 0.2 -> output impact ~1e-5 (verified in R15:
// rel_err 2.2413e-4 -> 2.2423e-4).
__device__ __forceinline__ float fast_atan2(float y, float x) {
    float ax = fabsf(x), ay = fabsf(y);
    float mx = fmaxf(ax, ay) + 1e-30f;
    float mn = fminf(ax, ay);
    float t = __fdividef(mn, mx);
    float s = t * t;
    float r = fmaf(fmaf(fmaf(-0.0464964749f, s, 0.15931422f), s, -0.327622764f),
                   s * t, t);
    if (ay > ax) r = 1.57079632679f - r;
    if (x < 0.0f) r = 3.14159265359f - r;
    return (y < 0.0f) ? -r : r;
}

// ------------- fused pre-pass: emdsum interleaved 2:1 with small work -------
#define EMD_WORK  (NN * (TT / 8))
#define NB_EMD    ((EMD_WORK + 255) / 256)     // 5860
#define NB_W      ((NN * 16 + 255) / 256)      // 1875
#define NB_UV     ((NN * NCC + 255) / 256)     // 586
#define NB_TAB    ((NCC * TT + 255) / 256)     // 8
#define NB_SMALL  (NB_UV + NB_W + NB_TAB)      // 2469
#define NB_PRE    (NB_EMD + NB_SMALL)          // 8329

__global__ void __launch_bounds__(256)
k_pre(const float* __restrict__ emd,
      const float* __restrict__ nbr_w,
      const float* __restrict__ loc_w,
      const float* __restrict__ esw,
      const float* __restrict__ lsw,
      const float* __restrict__ amp,
      const float* __restrict__ ph,
      const int*   __restrict__ idx,
      const float* __restrict__ tv,
      const float* __restrict__ per) {
    int b = blockIdx.x;
    int tid = threadIdx.x;
    bool is_small = ((b % 3) == 2) && (b / 3 < NB_SMALL);

    if (!is_small) {
        // ---- emdsum -> bf16 (DRAM-bound bulk) ----
        int nsmall_before = min((b + 1) / 3, NB_SMALL);
        int eb = b - nsmall_before;
        int i = eb * 256 + tid;
        if (i < EMD_WORK) {
            int n = i / (TT / 8);
            int t8 = i - n * (TT / 8);
            const float4* base = reinterpret_cast<const float4*>(emd + (size_t)n * 4 * TT);
            float r[8];
#pragma unroll
            for (int e = 0; e < 8; e++) r[e] = 0.0f;
#pragma unroll
            for (int c = 0; c < 4; c++) {
                float4 a = base[c * T4 + 2 * t8];
                float4 bb = base[c * T4 + 2 * t8 + 1];
                r[0] += a.x;  r[1] += a.y;  r[2] += a.z;  r[3] += a.w;
                r[4] += bb.x; r[5] += bb.y; r[6] += bb.z; r[7] += bb.w;
            }
            __nv_bfloat162 h[4];
#pragma unroll
            for (int e = 0; e < 4; e++)
                h[e] = __floats2bfloat162_rn(r[2 * e], r[2 * e + 1]);
            reinterpret_cast<uint4*>(g_emd + (size_t)n * TT)[t8] =
                *reinterpret_cast<uint4*>(h);
        }
        cudaTriggerProgrammaticLaunchCompletion();
        return;
    }

    int s = b / 3;   // small-work id, UV first (longest latency chains)
    if (s < NB_UV) {
        int i = s * 256 + tid;
        if (i < NN * NCC) {
            int n = i / NCC;
            int c = i - n * NCC;
            float sa = 0.0f, ss = 0.0f, sc = 0.0f;
#pragma unroll
            for (int k = 0; k < KK; k++) {
                int m = idx[n * KK + k];
                float w = nbr_w[n * KK + k];
                sa += w * amp[m * NCC + c];
                float p = ph[m * NCC + c];
                float si, co;
                __sincosf(p, &si, &co);
                ss += w * si;
                sc += w * co;
            }
            float A = 0.8f * amp[i] + 0.2f * sa;
            float P = 0.8f * ph[i] + 0.2f * fast_atan2(ss, sc);
            float sp, cp;
            __sincosf(P, &sp, &cp);
            g_UV[n * 10 + c] = A * cp;
            g_UV[n * 10 + 5 + c] = A * sp;
        }
        cudaTriggerProgrammaticLaunchCompletion();
        return;
    }
    s -= NB_UV;
    if (s < NB_W) {
        int i = s * 256 + tid;
        if (i < NN * 16) {
            int n = i >> 4;
            int j = i & 15;
            float ew = 1.0f / (1.0f + __expf(-esw[n]));
            if (j == 0) {
                g_W[i] = 1.0f - ew;
            } else {
                float lw = 1.0f / (1.0f + __expf(-lsw[n]));
                int k = j - 1;
                g_W[i] = ew * lw * loc_w[n * KK + k]
                       + ew * (1.0f - lw) * nbr_w[n * KK + k];
            }
        }
        cudaTriggerProgrammaticLaunchCompletion();
        return;
    }
    s -= NB_W;
    {
        int i = s * 256 + tid;
        if (i < NCC * TT) {
            int c = i / TT;
            int t = i - c * TT;
            float p = fminf(fmaxf(per[c], 15.0f), 350.0f);
            float arg = 6.283185307179586f * tv[t] / p;
            float si, co;
            sincosf(arg, &si, &co);
            g_tab[i] = si;
            g_tab[NCC * TT + i] = co;
        }
        cudaTriggerProgrammaticLaunchCompletion();
    }
}

// ======== shared compute body for both main kernels =========================
extern __shared__ __align__(1024) __nv_bfloat16 s_buf[];  // 2 * 12800 B

struct MainSmem {
    unsigned long long full[2];
    int   idxs[GG][ROWS];   // [0]=self, [1..15]=neighbors
    float W[GG][16];
    float UV[GG][10];
    float off[GG];
    float tr[GG];
};

// prologue A: depends ONLY on harness inputs — safe before griddep sync
__device__ __forceinline__ void prologue_inputs(
    MainSmem& sm, const int* __restrict__ idx,
    const float* __restrict__ coff, const float* __restrict__ ltr,
    const float* __restrict__ tv, int n0, int tid, float4& tv4, bool act) {
    if (tid < GG * KK) sm.idxs[tid / KK][tid % KK + 1] = idx[n0 * KK + tid];
    if (tid < GG) {
        sm.off[tid] = coff[n0 + tid];
        sm.tr[tid] = ltr[n0 + tid];
        sm.idxs[tid][0] = n0 + tid;
    }
    if (tid == 0) {
        uint32_t f0 = smem_u32(&sm.full[0]);
        mbar_init(f0, 1);
        mbar_init(f0 + 8, 1);
        asm volatile("fence.proxy.async.shared::cta;" ::: "memory");
    }
    if (act) tv4 = reinterpret_cast<const float4*>(tv)[tid];
}

// prologue B: reads pre-pass outputs — AFTER griddep sync.
// Register-resident sin/cos table (proven — do NOT evict).
__device__ __forceinline__ void prologue_tables(
    MainSmem& sm, int n0, int tid, float4* st, float4* ct, bool act) {
    if (tid < GG * 16) sm.W[tid >> 4][tid & 15] = g_W[n0 * 16 + tid];
    if (tid < GG * 10) sm.UV[tid / 10][tid % 10] = g_UV[n0 * 10 + tid];
    if (act) {
#pragma unroll
        for (int c = 0; c < NCC; c++) {
            st[c] = reinterpret_cast<const float4*>(g_tab + c * TT)[tid];
            ct[c] = reinterpret_cast<const float4*>(g_tab + NCC * TT + c * TT)[tid];
        }
    }
}

__device__ __forceinline__ void stage_compute(
    MainSmem& sm, int i, int n, int tid, bool act,
    const float4* st, const float4* ct, float4 tv4, float* __restrict__ out) {
    if (!act) return;
    const uint32_t* rows = reinterpret_cast<const uint32_t*>(
        s_buf + (size_t)(i & 1) * (ROWS * TT));
    float off = sm.off[i], tr = sm.tr[i];
    float4 acc;
    acc.x = fmaf(tr, tv4.x, off);
    acc.y = fmaf(tr, tv4.y, off);
    acc.z = fmaf(tr, tv4.z, off);
    acc.w = fmaf(tr, tv4.w, off);
#pragma unroll
    for (int c = 0; c < NCC; c++) {
        float u = sm.UV[i][c], v = sm.UV[i][5 + c];
        acc.x = fmaf(u, st[c].x, fmaf(v, ct[c].x, acc.x));
        acc.y = fmaf(u, st[c].y, fmaf(v, ct[c].y, acc.y));
        acc.z = fmaf(u, st[c].z, fmaf(v, ct[c].z, acc.z));
        acc.w = fmaf(u, st[c].w, fmaf(v, ct[c].w, acc.w));
    }
#pragma unroll
    for (int j = 0; j < ROWS; j++) {
        uint2 raw = *reinterpret_cast<const uint2*>(rows + j * 200 + 2 * tid);
        float w = sm.W[i][j];
        acc.x = fmaf(w, bf_lo(raw.x), acc.x);
        acc.y = fmaf(w, bf_hi(raw.x), acc.y);
        acc.z = fmaf(w, bf_lo(raw.y), acc.z);
        acc.w = fmaf(w, bf_hi(raw.y), acc.w);
    }
    reinterpret_cast<float4*>(out + (size_t)n * TT)[tid] = acc;
}

// ---------------- k_main_g4: gather4 path (4 TMA requests per stage) --------
__global__ void __launch_bounds__(128, 8)
k_main_g4(const __grid_constant__ CUtensorMap tmap,
          const int* __restrict__ idx,
          const float* __restrict__ coff,
          const float* __restrict__ ltr,
          const float* __restrict__ tv,
          float* __restrict__ out) {
    __shared__ MainSmem sm;
    int tid = threadIdx.x;
    int n0 = blockIdx.x * GG;
    bool act = (tid < T4);
    float4 st[NCC], ct[NCC], tv4;
    prologue_inputs(sm, idx, coff, ltr, tv, n0, tid, tv4, act);

    cudaGridDependencySynchronize();   // PDL: g_* visible after this

    prologue_tables(sm, n0, tid, st, ct, act);
    __syncthreads();

    uint32_t full0 = smem_u32(&sm.full[0]);
    uint32_t bufb  = smem_u32(s_buf);

    auto issue = [&](int s) {
        uint32_t dst = bufb + (uint32_t)(s & 1) * STAGEBYTES;
        uint32_t mb  = full0 + (uint32_t)(s & 1) * 8;
        mbar_expect_tx(mb, STAGEBYTES);
        const int* r = sm.idxs[s];
#pragma unroll
        for (int q = 0; q < 4; q++) {
            g4(dst + (uint32_t)q * (4 * ROWBYTES), &tmap,
               r[4 * q], r[4 * q + 1], r[4 * q + 2], r[4 * q + 3], mb);
        }
    };

    if (tid == 0) issue(0);
    for (int i = 0; i < GG; i++) {
        if (tid == 0 && i + 1 < GG) issue(i + 1);
        mbar_wait(full0 + (uint32_t)(i & 1) * 8, (uint32_t)((i >> 1) & 1));
        stage_compute(sm, i, n0 + i, tid, act, st, ct, tv4, out);
        __syncthreads();
    }
}

// ---------------- k_main_fb: bulk-copy fallback ------------------------------
__global__ void __launch_bounds__(128, 8)
k_main_fb(const int* __restrict__ idx,
          const float* __restrict__ coff,
          const float* __restrict__ ltr,
          const float* __restrict__ tv,
          float* __restrict__ out) {
    __shared__ MainSmem sm;
    int tid = threadIdx.x;
    int n0 = blockIdx.x * GG;
    bool act = (tid < T4);
    float4 st[NCC], ct[NCC], tv4;
    prologue_inputs(sm, idx, coff, ltr, tv, n0, tid, tv4, act);

    cudaGridDependencySynchronize();

    prologue_tables(sm, n0, tid, st, ct, act);
    __syncthreads();

    uint32_t full0 = smem_u32(&sm.full[0]);
    uint32_t bufb  = smem_u32(s_buf);

    auto issue = [&](int s) {
        uint32_t dst = bufb + (uint32_t)(s & 1) * STAGEBYTES;
        uint32_t mb  = full0 + (uint32_t)(s & 1) * 8;
        mbar_expect_tx(mb, STAGEBYTES);
#pragma unroll
        for (int k = 0; k < ROWS; k++) {
            bulk_g2s(dst + (uint32_t)k * ROWBYTES,
                     g_emd + (size_t)sm.idxs[s][k] * TT, ROWBYTES, mb);
        }
    };

    if (tid == 0) issue(0);
    for (int i = 0; i < GG; i++) {
        if (tid == 0 && i + 1 < GG) issue(i + 1);
        mbar_wait(full0 + (uint32_t)(i & 1) * 8, (uint32_t)((i >> 1) & 1));
        stage_compute(sm, i, n0 + i, tid, act, st, ct, tv4, out);
        __syncthreads();
    }
}

// ---------------- launch ----------------
typedef CUresult (*EncodeFn)(CUtensorMap*, CUtensorMapDataType, cuuint32_t,
                             void*, const cuuint64_t*, const cuuint64_t*,
                             const cuuint32_t*, const cuuint32_t*,
                             CUtensorMapInterleave, CUtensorMapSwizzle,
                             CUtensorMapL2promotion, CUtensorMapFloatOOBfill);

extern "C" void kernel_launch(void* const* d_in, const int* in_sizes, int n_in,
                              void* d_out, int out_size) {
    const float* tv   = (const float*)d_in[0];
    const float* coff = (const float*)d_in[1];
    const float* ltr  = (const float*)d_in[2];
    const float* emd  = (const float*)d_in[3];
    const int*   idx  = (const int*)  d_in[4];
    const float* nw   = (const float*)d_in[5];
    const float* lwv  = (const float*)d_in[6];
    const float* amp  = (const float*)d_in[7];
    const float* ph   = (const float*)d_in[8];
    const float* per  = (const float*)d_in[9];
    const float* esw  = (const float*)d_in[10];
    const float* lsw  = (const float*)d_in[11];
    float* out = (float*)d_out;

    k_pre<<<NB_PRE, 256>>>(emd, nw, lwv, esw, lsw, amp, ph, idx, tv, per);

    // Build gather4 tensormap: view g_emd as u32 tensor [NN rows x 200 cols]
    bool g4ok = false;
    CUtensorMap tmap;
    {
        void* fn = nullptr;
        cudaDriverEntryPointQueryResult qres;
        if (cudaGetDriverEntryPoint("cuTensorMapEncodeTiled", &fn,
                                    cudaEnableDefault, &qres) == cudaSuccess &&
            fn != nullptr) {
            void* gaddr = nullptr;
            if (cudaGetSymbolAddress(&gaddr, g_emd) == cudaSuccess) {
                cuuint64_t dims[2]    = {200, NN};
                cuuint64_t strides[1] = {ROWBYTES};   // 800 B between rows
                cuuint32_t box[2]     = {200, 1};
                cuuint32_t estr[2]    = {1, 1};
                CUresult r = ((EncodeFn)fn)(
                    &tmap, CU_TENSOR_MAP_DATA_TYPE_UINT32, 2, gaddr,
                    dims, strides, box, estr,
                    CU_TENSOR_MAP_INTERLEAVE_NONE, CU_TENSOR_MAP_SWIZZLE_NONE,
                    CU_TENSOR_MAP_L2_PROMOTION_L2_128B,
                    CU_TENSOR_MAP_FLOAT_OOB_FILL_NONE);
                g4ok = (r == CUDA_SUCCESS);
            }
        }
    }

    cudaFuncSetAttribute(k_main_g4, cudaFuncAttributeMaxDynamicSharedMemorySize,
                         2 * STAGEBYTES);
    cudaFuncSetAttribute(k_main_fb, cudaFuncAttributeMaxDynamicSharedMemorySize,
                         2 * STAGEBYTES);

    // PDL launch: k_main's launch + input-only prologue overlap k_pre's tail
    cudaLaunchConfig_t cfg = {};
    cfg.gridDim = dim3(NN / GG, 1, 1);
    cfg.blockDim = dim3(128, 1, 1);
    cfg.dynamicSmemBytes = 2 * STAGEBYTES;
    cudaLaunchAttribute attrs[1];
    attrs[0].id = cudaLaunchAttributeProgrammaticStreamSerialization;
    attrs[0].val.programmaticStreamSerializationAllowed = 1;
    cfg.attrs = attrs;
    cfg.numAttrs = 1;

    if (g4ok) {
        cudaError_t e = cudaLaunchKernelEx(&cfg, k_main_g4,
                                           tmap, idx, coff, ltr, tv, out);
        if (e != cudaSuccess)
            k_main_g4<<<NN / GG, 128, 2 * STAGEBYTES>>>(tmap, idx, coff, ltr, tv, out);
    } else {
        cudaError_t e = cudaLaunchKernelEx(&cfg, k_main_fb,
                                           idx, coff, ltr, tv, out);
        if (e != cudaSuccess)
            k_main_fb<<<NN / GG, 128, 2 * STAGEBYTES>>>(idx, coff, ltr, tv, out);
    }
}